// round 1
// baseline (speedup 1.0000x reference)
#include <cuda_runtime.h>
#include <math.h>

#define N_ROWS_MAX 100000
#define D 64
#define NGH 16
#define NSC 10
#define EPSF 1e-10f

// Scratch (25.6 MB + 0.4 MB) — device globals per allocation rules.
__device__ float g_row_sum[(size_t)N_ROWS_MAX * D];
__device__ float g_inv[N_ROWS_MAX];

// ---------------------------------------------------------------------------
// Kernel A: row_sum[j] = sum_k scene_emb[cate_scene_pad[j,k]]  and
//           inv[j] = 1 / (||row_sum[j]||^2 + eps)
// 16 threads per row, float4 per thread (64 floats = 16 lanes * 4).
// ---------------------------------------------------------------------------
__global__ void rowsum_kernel(const float* __restrict__ scene_emb,
                              const int* __restrict__ cate_scene_pad,
                              int n_rows) {
    int tid = blockIdx.x * blockDim.x + threadIdx.x;
    int row = tid >> 4;
    int sub = tid & 15;          // 0..15 within the 16-lane group
    if (row >= n_rows) return;
    int lane = threadIdx.x & 31;
    int group_base = lane & 16;  // 0 for lanes 0-15, 16 for lanes 16-31

    // lanes 0..9 of each half-warp hold the 10 scene indices for their row
    int myidx = 0;
    if (sub < NSC) myidx = cate_scene_pad[(size_t)row * NSC + sub];

    float4 acc = make_float4(0.f, 0.f, 0.f, 0.f);
#pragma unroll
    for (int k = 0; k < NSC; k++) {
        int j = __shfl_sync(0xFFFFFFFFu, myidx, group_base + k);
        float4 v = ((const float4*)(scene_emb + (size_t)j * D))[sub];
        acc.x += v.x; acc.y += v.y; acc.z += v.z; acc.w += v.w;
    }

    // squared norm, reduced across the 16-lane group (xor offsets < 16 stay in-group)
    float sq = acc.x * acc.x + acc.y * acc.y + acc.z * acc.z + acc.w * acc.w;
#pragma unroll
    for (int o = 8; o >= 1; o >>= 1)
        sq += __shfl_xor_sync(0xFFFFFFFFu, sq, o);

    ((float4*)(g_row_sum + (size_t)row * D))[sub] = acc;
    if (sub == 0) g_inv[row] = 1.0f / (sq + EPSF);
}

// ---------------------------------------------------------------------------
// Kernel B: per-row attention over {self, 16 neighbors} + aggregation +
//           64x128 matvec + ELU.  One warp per row, float2 per lane.
// ---------------------------------------------------------------------------
__global__ void __launch_bounds__(256, 4)
main_kernel(const float* __restrict__ cate_emb,
            const int* __restrict__ c_cate_pad,
            const float* __restrict__ agg_W,
            const float* __restrict__ agg_b,
            float* __restrict__ out,
            int n_rows, int v_cates) {
    // Wt[e][d] with row pad 65 -> bank-conflict-free transpose store and read
    __shared__ float sW[128 * 65];
    __shared__ float sH[8][128];

    int warp = threadIdx.x >> 5;
    int lane = threadIdx.x & 31;

    // stage W transposed: agg_W is [64][128] row-major; sW[e*65+d] = W[d][e]
    for (int idx = threadIdx.x; idx < 64 * 128; idx += blockDim.x) {
        int d = idx >> 7;
        int e = idx & 127;
        sW[e * 65 + d] = agg_W[idx];
    }
    __syncthreads();

    int row = blockIdx.x * 8 + warp;
    if (row < n_rows) {
        int nidx = (lane < NGH) ? c_cate_pad[(size_t)row * NGH + lane] : 0;

        float2 a = ((const float2*)(g_row_sum + (size_t)row * D))[lane];
        float invL = g_inv[row];

        float agg0 = 0.f, agg1 = 0.f, denom = 0.f;
#pragma unroll
        for (int i = 0; i < 17; i++) {
            int p = (i == 0) ? row : __shfl_sync(0xFFFFFFFFu, nidx, i - 1);
            float2 r = ((const float2*)(g_row_sum + (size_t)p * D))[lane];
            float dot = a.x * r.x + a.y * r.y;
#pragma unroll
            for (int o = 16; o >= 1; o >>= 1)
                dot += __shfl_xor_sync(0xFFFFFFFFu, dot, o);

            float miu = 0.f;
            if (p < v_cates - 1) {        // mask: pad id = v_cates-1 (and beyond)
                float sim = dot * invL * g_inv[p];
                miu = expf(sim);
            }
            denom += miu;
            float2 ce = ((const float2*)(cate_emb + (size_t)p * D))[lane];
            agg0 = fmaf(miu, ce.x, agg0);
            agg1 = fmaf(miu, ce.y, agg1);
        }
        float rden = 1.0f / (denom + EPSF);
        agg0 *= rden; agg1 *= rden;

        // h = concat(row_sum[row], agg) in shared
        ((float2*)sH[warp])[lane]      = a;
        ((float2*)sH[warp])[32 + lane] = make_float2(agg0, agg1);
    }
    __syncwarp();

    if (row < n_rows) {
        int d0 = lane, d1 = lane + 32;
        float acc0 = agg_b[d0];
        float acc1 = agg_b[d1];
#pragma unroll 16
        for (int e = 0; e < 128; e++) {
            float h = sH[warp][e];
            acc0 = fmaf(sW[e * 65 + d0], h, acc0);
            acc1 = fmaf(sW[e * 65 + d1], h, acc1);
        }
        float* o = out + (size_t)row * D;
        o[d0] = acc0 > 0.f ? acc0 : expm1f(acc0);
        o[d1] = acc1 > 0.f ? acc1 : expm1f(acc1);
    }
}

// ---------------------------------------------------------------------------
// Inputs (metadata order):
//  0 cids            int32  [N]        (unused by forward)
//  1 cate_emb_w      f32    [Vc, 64]
//  2 scene_emb_w     f32    [Vs, 64]
//  3 cate_scene_pad  int32  [N, 10]
//  4 c_cate_pad      int32  [N, 16]
//  5 agg_W           f32    [64, 128]
//  6 agg_b           f32    [64]
// out: f32 [N, 64]
// ---------------------------------------------------------------------------
extern "C" void kernel_launch(void* const* d_in, const int* in_sizes, int n_in,
                              void* d_out, int out_size) {
    const float* cate_emb       = (const float*)d_in[1];
    const float* scene_emb      = (const float*)d_in[2];
    const int*   cate_scene_pad = (const int*)d_in[3];
    const int*   c_cate_pad     = (const int*)d_in[4];
    const float* agg_W          = (const float*)d_in[5];
    const float* agg_b          = (const float*)d_in[6];
    float* out = (float*)d_out;

    int n_rows  = in_sizes[4] / NGH;   // 100000
    int v_cates = in_sizes[1] / D;     // 100000

    int threadsA = 256;
    int blocksA = (n_rows * 16 + threadsA - 1) / threadsA;
    rowsum_kernel<<<blocksA, threadsA>>>(scene_emb, cate_scene_pad, n_rows);

    int blocksB = (n_rows + 7) / 8;
    main_kernel<<<blocksB, 256>>>(cate_emb, c_cate_pad, agg_W, agg_b,
                                  out, n_rows, v_cates);
}

// round 2
// speedup vs baseline: 1.4024x; 1.4024x over previous
#include <cuda_runtime.h>
#include <math.h>

#define N_ROWS_MAX 100000
#define D 64
#define NGH 16
#define NSC 10
#define EPSF 1e-10f

#define RPW 8          // rows per warp
#define WPB 8          // warps per block
#define RPB (RPW*WPB)  // rows per block = 64
#define WSTRIDE 132    // padded W row stride (floats) -> conflict-free float4 LDS

// Scratch — device globals per allocation rules.
__device__ float g_row_sum[(size_t)N_ROWS_MAX * D];
__device__ float g_inv[N_ROWS_MAX];

// ---------------------------------------------------------------------------
// Kernel A: row_sum[j] = sum_k scene_emb[cate_scene_pad[j,k]],
//           inv[j] = 1 / (||row_sum[j]||^2 + eps)
// 16 threads per row, float4 per thread.
// ---------------------------------------------------------------------------
__global__ void rowsum_kernel(const float* __restrict__ scene_emb,
                              const int* __restrict__ cate_scene_pad,
                              int n_rows) {
    int tid = blockIdx.x * blockDim.x + threadIdx.x;
    int row = tid >> 4;
    int sub = tid & 15;
    if (row >= n_rows) return;
    int lane = threadIdx.x & 31;
    int group_base = lane & 16;

    int myidx = 0;
    if (sub < NSC) myidx = __ldg(cate_scene_pad + (size_t)row * NSC + sub);

    float4 acc = make_float4(0.f, 0.f, 0.f, 0.f);
#pragma unroll
    for (int k = 0; k < NSC; k++) {
        int j = __shfl_sync(0xFFFFFFFFu, myidx, group_base + k);
        float4 v = ((const float4*)(scene_emb + (size_t)j * D))[sub];
        acc.x += v.x; acc.y += v.y; acc.z += v.z; acc.w += v.w;
    }

    float sq = acc.x * acc.x + acc.y * acc.y + acc.z * acc.z + acc.w * acc.w;
#pragma unroll
    for (int o = 8; o >= 1; o >>= 1)
        sq += __shfl_xor_sync(0xFFFFFFFFu, sq, o);

    ((float4*)(g_row_sum + (size_t)row * D))[sub] = acc;
    if (sub == 0) g_inv[row] = 1.0f / (sq + EPSF);
}

// ---------------------------------------------------------------------------
// Kernel B: one warp owns 8 rows.
//   Phase 1 (per row): attention over {self, 16 ngh} -> h[128] in shared.
//   Phase 2: warp-tiled matvec out[8][64] = h[8][128] @ W^T, W read once
//            per 8 rows from shared (stride-132 layout, conflict-free float4).
// ---------------------------------------------------------------------------
__global__ void __launch_bounds__(256, 3)
main_kernel(const float* __restrict__ cate_emb,
            const int* __restrict__ c_cate_pad,
            const float* __restrict__ agg_W,
            const float* __restrict__ agg_b,
            float* __restrict__ out,
            int n_rows, int v_cates) {
    extern __shared__ float smem[];
    float* sW = smem;                    // 64 * 132 floats
    float* sH = smem + 64 * WSTRIDE;     // 8 warps * 8 rows * 128 floats

    int tid  = threadIdx.x;
    int warp = tid >> 5;
    int lane = tid & 31;

    // Stage W: agg_W is [64][128] row-major; sW[d*132 + e] = W[d][e]
    const float4* Wv = (const float4*)agg_W;
    for (int idx = tid; idx < 64 * 32; idx += 256) {
        int d = idx >> 5;
        int c = idx & 31;
        float4 v = Wv[idx];
        *(float4*)(sW + d * WSTRIDE + 4 * c) = v;
    }
    __syncthreads();

    int rowbase = blockIdx.x * RPB + warp * RPW;
    float* sHw = sH + warp * (RPW * 128);

    // ---- Phase 1: attention per row ----
#pragma unroll 1
    for (int r = 0; r < RPW; r++) {
        int row = rowbase + r;
        if (row >= n_rows) break;

        int nidx = 0;
        if (lane < NGH) nidx = __ldg(c_cate_pad + (size_t)row * NGH + lane);

        int pid[17];
        pid[0] = row;
#pragma unroll
        for (int i = 1; i < 17; i++)
            pid[i] = __shfl_sync(0xFFFFFFFFu, nidx, i - 1);

        float2 a = *(const float2*)(g_row_sum + (size_t)row * D + 2 * lane);
        float invL = g_inv[row];

        float agg0 = 0.f, agg1 = 0.f, denom = 0.f;
#pragma unroll
        for (int i = 0; i < 17; i++) {
            int p = pid[i];
            float2 rsv = (i == 0) ? a
                       : *(const float2*)(g_row_sum + (size_t)p * D + 2 * lane);
            float2 cev = *(const float2*)(cate_emb + (size_t)p * D + 2 * lane);

            float dot = rsv.x * a.x + rsv.y * a.y;
#pragma unroll
            for (int o = 16; o >= 1; o >>= 1)
                dot += __shfl_xor_sync(0xFFFFFFFFu, dot, o);

            float miu = 0.f;
            if (p < v_cates - 1)
                miu = __expf(dot * invL * g_inv[p]);

            denom += miu;
            agg0 = fmaf(miu, cev.x, agg0);
            agg1 = fmaf(miu, cev.y, agg1);
        }
        float rden = 1.0f / (denom + EPSF);

        float2* hh = (float2*)(sHw + r * 128);
        hh[lane]      = a;
        hh[32 + lane] = make_float2(agg0 * rden, agg1 * rden);
    }
    __syncwarp();

    // ---- Phase 2: warp-tiled matvec, 8 rows x (2 cols/lane) ----
    float acc0[RPW], acc1[RPW];
#pragma unroll
    for (int r = 0; r < RPW; r++) { acc0[r] = 0.f; acc1[r] = 0.f; }

    const float* w0p = sW + lane * WSTRIDE;
    const float* w1p = sW + (lane + 32) * WSTRIDE;

#pragma unroll 4
    for (int c = 0; c < 32; c++) {
        float4 w0 = *(const float4*)(w0p + 4 * c);
        float4 w1 = *(const float4*)(w1p + 4 * c);
#pragma unroll
        for (int r = 0; r < RPW; r++) {
            float4 h4 = *(const float4*)(sHw + r * 128 + 4 * c);
            acc0[r] = fmaf(w0.x, h4.x, fmaf(w0.y, h4.y,
                      fmaf(w0.z, h4.z, fmaf(w0.w, h4.w, acc0[r]))));
            acc1[r] = fmaf(w1.x, h4.x, fmaf(w1.y, h4.y,
                      fmaf(w1.z, h4.z, fmaf(w1.w, h4.w, acc1[r]))));
        }
    }

    float b0 = __ldg(agg_b + lane);
    float b1 = __ldg(agg_b + lane + 32);
#pragma unroll
    for (int r = 0; r < RPW; r++) {
        int row = rowbase + r;
        if (row < n_rows) {
            float v0 = acc0[r] + b0;
            float v1 = acc1[r] + b1;
            float* o = out + (size_t)row * D;
            o[lane]      = v0 > 0.f ? v0 : expm1f(v0);
            o[32 + lane] = v1 > 0.f ? v1 : expm1f(v1);
        }
    }
}

// ---------------------------------------------------------------------------
// Inputs (metadata order):
//  0 cids            int32  [N]       (unused by forward)
//  1 cate_emb_w      f32    [Vc, 64]
//  2 scene_emb_w     f32    [Vs, 64]
//  3 cate_scene_pad  int32  [N, 10]
//  4 c_cate_pad      int32  [N, 16]
//  5 agg_W           f32    [64, 128]
//  6 agg_b           f32    [64]
// out: f32 [N, 64]
// ---------------------------------------------------------------------------
extern "C" void kernel_launch(void* const* d_in, const int* in_sizes, int n_in,
                              void* d_out, int out_size) {
    const float* cate_emb       = (const float*)d_in[1];
    const float* scene_emb      = (const float*)d_in[2];
    const int*   cate_scene_pad = (const int*)d_in[3];
    const int*   c_cate_pad     = (const int*)d_in[4];
    const float* agg_W          = (const float*)d_in[5];
    const float* agg_b          = (const float*)d_in[6];
    float* out = (float*)d_out;

    int n_rows  = in_sizes[4] / NGH;   // 100000
    int v_cates = in_sizes[1] / D;     // 100000

    int threadsA = 256;
    int blocksA = (n_rows * 16 + threadsA - 1) / threadsA;
    rowsum_kernel<<<blocksA, threadsA>>>(scene_emb, cate_scene_pad, n_rows);

    int smem_bytes = (64 * WSTRIDE + WPB * RPW * 128) * (int)sizeof(float);
    cudaFuncSetAttribute(main_kernel,
                         cudaFuncAttributeMaxDynamicSharedMemorySize, smem_bytes);
    int blocksB = (n_rows + RPB - 1) / RPB;
    main_kernel<<<blocksB, 256, smem_bytes>>>(cate_emb, c_cate_pad, agg_W, agg_b,
                                              out, n_rows, v_cates);
}

// round 3
// speedup vs baseline: 1.8710x; 1.3342x over previous
#include <cuda_runtime.h>
#include <math.h>

#define N_ROWS_MAX 100000
#define D 64
#define NGH 16
#define NSC 10
#define EPSF 1e-10f
#define FULL 0xFFFFFFFFu

#define RPW 8          // rows per warp
#define WPB 8          // warps per block
#define RPB (RPW*WPB)  // rows per block = 64

// Scratch — device globals per allocation rules.
__device__ float  g_rs_hat[(size_t)N_ROWS_MAX * D];  // rs / (||rs||^2+eps)
__device__ float2 g_ss[N_ROWS_MAX];                  // (scale = sq+eps, selfsim = sq/(sq+eps)^2)
__device__ float4 g_W4[64 * 32];                     // [c][d] = W[d][4c..4c+3]

// ---------------------------------------------------------------------------
// Kernel A: per-row scene sums (scaled), self-sim scalars; blocks 0-7 also
// transpose agg_W into g_W4.
// ---------------------------------------------------------------------------
__global__ void rowsum_kernel(const float* __restrict__ scene_emb,
                              const int* __restrict__ cate_scene_pad,
                              const float* __restrict__ agg_W,
                              int n_rows) {
    int gtid = blockIdx.x * blockDim.x + threadIdx.x;
    // W transpose prep: first 2048 threads, one float4 each.
    if (gtid < 64 * 32) {
        int d = gtid & 63;
        int c = gtid >> 6;
        g_W4[c * 64 + d] = ((const float4*)agg_W)[d * 32 + c];
    }

    int row = gtid >> 4;
    int sub = gtid & 15;
    if (row >= n_rows) return;
    int lane = threadIdx.x & 31;
    int group_base = lane & 16;

    int myidx = 0;
    if (sub < NSC) myidx = __ldg(cate_scene_pad + (size_t)row * NSC + sub);

    float4 acc = make_float4(0.f, 0.f, 0.f, 0.f);
#pragma unroll
    for (int k = 0; k < NSC; k++) {
        int j = __shfl_sync(FULL, myidx, group_base + k);
        float4 v = ((const float4*)(scene_emb + (size_t)j * D))[sub];
        acc.x += v.x; acc.y += v.y; acc.z += v.z; acc.w += v.w;
    }

    float sq = acc.x * acc.x + acc.y * acc.y + acc.z * acc.z + acc.w * acc.w;
#pragma unroll
    for (int o = 8; o >= 1; o >>= 1)
        sq += __shfl_xor_sync(FULL, sq, o);

    float scale = sq + EPSF;
    float inv = 1.0f / scale;
    acc.x *= inv; acc.y *= inv; acc.z *= inv; acc.w *= inv;
    ((float4*)(g_rs_hat + (size_t)row * D))[sub] = acc;
    if (sub == 0) g_ss[row] = make_float2(scale, sq * inv * inv);
}

// Butterfly merge: combine two lane-distributed partial sums at xor-offset o.
// Result: lanes with (lane&o)==0 carry a-pairs, others carry b-pairs.
__device__ __forceinline__ float bmerge(float a, float b, int o, int lane) {
    float x = (lane & o) ? b : a;
    float y = (lane & o) ? a : b;
    y = __shfl_xor_sync(FULL, y, o);
    return x + y;
}

// ---------------------------------------------------------------------------
// Kernel B: one warp owns 8 rows. Attention -> h in shared; then register-
// tiled matvec with W streamed from L1-resident g_W4.
// ---------------------------------------------------------------------------
__global__ void __launch_bounds__(256, 4)
main_kernel(const float* __restrict__ cate_emb,
            const int* __restrict__ c_cate_pad,
            const float* __restrict__ agg_b,
            float* __restrict__ out,
            int n_rows, int v_cates) {
    __shared__ float sH[WPB][RPW * 128];

    int tid  = threadIdx.x;
    int warp = tid >> 5;
    int lane = tid & 31;

    int rowbase = blockIdx.x * RPB + warp * RPW;
    float* sHw = sH[warp];

    const float2* rs2 = (const float2*)g_rs_hat;
    const float2* ce2 = (const float2*)cate_emb;

    // ---- Phase 1: attention per row ----
#pragma unroll 1
    for (int r = 0; r < RPW; r++) {
        int row = rowbase + r;
        if (row >= n_rows) break;

        int nidx = 0;
        if (lane < NGH) nidx = __ldg(c_cate_pad + (size_t)row * NGH + lane);

        float2 a  = rs2[(size_t)row * 32 + lane];
        float2 ss = g_ss[row];                 // (scale, selfsim)

        // 16 neighbor dot partials (independent gathers)
        float dtp[16];
#pragma unroll
        for (int j = 0; j < 16; j++) {
            int p = __shfl_sync(FULL, nidx, j);
            float2 rv = rs2[(size_t)p * 32 + lane];
            dtp[j] = fmaf(rv.x, a.x, rv.y * a.y);
        }

        // Butterfly merge tree: lane L ends with full dot for j = L>>1
#pragma unroll
        for (int i = 0; i < 8; i++) dtp[i] = bmerge(dtp[i], dtp[i + 8], 16, lane);
#pragma unroll
        for (int i = 0; i < 4; i++) dtp[i] = bmerge(dtp[i], dtp[i + 4],  8, lane);
#pragma unroll
        for (int i = 0; i < 2; i++) dtp[i] = bmerge(dtp[i], dtp[i + 2],  4, lane);
        dtp[0] = bmerge(dtp[0], dtp[1], 2, lane);
        dtp[0] += __shfl_xor_sync(FULL, dtp[0], 1);

        // miu_j at lanes 2j, 2j+1
        int jj = lane >> 1;
        int pj = __shfl_sync(FULL, nidx, jj);
        float miu = (pj < v_cates - 1) ? __expf(dtp[0]) : 0.f;

        // denom across distinct j
        float dv = (lane & 1) ? 0.f : miu;
#pragma unroll
        for (int o = 16; o >= 1; o >>= 1)
            dv += __shfl_xor_sync(FULL, dv, o);

        float miu_self = (row < v_cates - 1) ? __expf(ss.y) : 0.f;
        float rden = 1.0f / (dv + miu_self + EPSF);

        // aggregation: self + 16 neighbors
        float2 c0 = ce2[(size_t)row * 32 + lane];
        float ax = miu_self * c0.x;
        float ay = miu_self * c0.y;
#pragma unroll
        for (int j = 0; j < 16; j++) {
            float m = __shfl_sync(FULL, miu, 2 * j);
            int   p = __shfl_sync(FULL, nidx, j);
            float2 cv = ce2[(size_t)p * 32 + lane];
            ax = fmaf(m, cv.x, ax);
            ay = fmaf(m, cv.y, ay);
        }

        float2* hh = (float2*)(sHw + r * 128);
        hh[lane]      = make_float2(a.x * ss.x, a.y * ss.x);   // raw row_sum
        hh[32 + lane] = make_float2(ax * rden, ay * rden);     // agg
    }
    __syncwarp();

    // ---- Phase 2: register-tiled matvec, 8 rows x 2 cols/lane ----
    float acc0[RPW], acc1[RPW];
#pragma unroll
    for (int r = 0; r < RPW; r++) { acc0[r] = 0.f; acc1[r] = 0.f; }

#pragma unroll 4
    for (int c = 0; c < 32; c++) {
        float4 w0 = __ldg(g_W4 + c * 64 + lane);
        float4 w1 = __ldg(g_W4 + c * 64 + 32 + lane);
#pragma unroll
        for (int r = 0; r < RPW; r++) {
            float4 h4 = *(const float4*)(sHw + r * 128 + 4 * c);
            acc0[r] = fmaf(w0.x, h4.x, fmaf(w0.y, h4.y,
                      fmaf(w0.z, h4.z, fmaf(w0.w, h4.w, acc0[r]))));
            acc1[r] = fmaf(w1.x, h4.x, fmaf(w1.y, h4.y,
                      fmaf(w1.z, h4.z, fmaf(w1.w, h4.w, acc1[r]))));
        }
    }

    float b0 = __ldg(agg_b + lane);
    float b1 = __ldg(agg_b + lane + 32);
#pragma unroll
    for (int r = 0; r < RPW; r++) {
        int row = rowbase + r;
        if (row < n_rows) {
            float v0 = acc0[r] + b0;
            float v1 = acc1[r] + b1;
            float* o = out + (size_t)row * D;
            o[lane]      = v0 > 0.f ? v0 : expm1f(v0);
            o[32 + lane] = v1 > 0.f ? v1 : expm1f(v1);
        }
    }
}

// ---------------------------------------------------------------------------
// Inputs (metadata order):
//  0 cids            int32  [N]       (unused by forward)
//  1 cate_emb_w      f32    [Vc, 64]
//  2 scene_emb_w     f32    [Vs, 64]
//  3 cate_scene_pad  int32  [N, 10]
//  4 c_cate_pad      int32  [N, 16]
//  5 agg_W           f32    [64, 128]
//  6 agg_b           f32    [64]
// out: f32 [N, 64]
// ---------------------------------------------------------------------------
extern "C" void kernel_launch(void* const* d_in, const int* in_sizes, int n_in,
                              void* d_out, int out_size) {
    const float* cate_emb       = (const float*)d_in[1];
    const float* scene_emb      = (const float*)d_in[2];
    const int*   cate_scene_pad = (const int*)d_in[3];
    const int*   c_cate_pad     = (const int*)d_in[4];
    const float* agg_W          = (const float*)d_in[5];
    const float* agg_b          = (const float*)d_in[6];
    float* out = (float*)d_out;

    int n_rows  = in_sizes[4] / NGH;   // 100000
    int v_cates = in_sizes[1] / D;     // 100000

    int threadsA = 256;
    int blocksA = (n_rows * 16 + threadsA - 1) / threadsA;
    rowsum_kernel<<<blocksA, threadsA>>>(scene_emb, cate_scene_pad, agg_W, n_rows);

    int blocksB = (n_rows + RPB - 1) / RPB;
    main_kernel<<<blocksB, 256>>>(cate_emb, c_cate_pad, agg_b,
                                  out, n_rows, v_cates);
}